// round 1
// baseline (speedup 1.0000x reference)
#include <cuda_runtime.h>
#include <math.h>

// Problem constants
#define DD        512
#define SEQLEN    4096
#define CHUNKSZ   256
#define NCHUNK    16
#define BATCH     4
#define ROWS      (BATCH*CHUNKSZ)   /* 1024 rows per chunk step */
#define HID       1024              /* 2*D */

// Scratch layout (floats) in one __device__ global
#define OFF_W1  ((size_t)0)          /* 512*1024  */
#define OFF_W2  ((size_t)524288)
#define OFF_S1  ((size_t)1048576)
#define OFF_S2  ((size_t)1572864)
#define OFF_K   ((size_t)2097152)    /* 1024*512  */
#define OFF_V   ((size_t)2621440)
#define OFF_DP  ((size_t)3145728)    /* dpred 1024*512 */
#define OFF_HG  ((size_t)3670016)    /* 1024*1024 */
#define OFF_GP  ((size_t)4718592)    /* 1024*1024 */
#define OFF_DH  ((size_t)5767168)    /* 1024*1024 */
#define OFF_Q   ((size_t)6815744)    /* 16384*512 */
#define OFF_HQ  ((size_t)15204352)   /* 16384*1024 */
#define SCRATCH_TOTAL ((size_t)31981568)

__device__ __align__(256) float g_scratch[SCRATCH_TOTAL];

__device__ __forceinline__ float geluf(float x) {
    return 0.5f * x * (1.0f + erff(x * 0.7071067811865476f));
}
__device__ __forceinline__ float gelugrad(float x) {
    float cdf = 0.5f * (1.0f + erff(x * 0.7071067811865476f));
    float pdf = 0.3989422804014327f * expf(-0.5f * x * x);
    return cdf + x * pdf;
}
__device__ __forceinline__ float sigm(float t) { return 1.0f / (1.0f + expf(-t)); }

enum { EPI_NONE = 0, EPI_GELU_BOTH = 1, EPI_GELU = 2, EPI_DPRED = 3, EPI_MULGP = 4, EPI_UPDATE = 5 };

// Tiled SGEMM: C[M,N] = op(A) @ op(B), 64x64 block tile, BK=16, 4x4 per thread.
// TRA=1: A stored [K,M] row-major (A^T used).  TRB=1: B stored [N,K] row-major (B^T used).
// ACHUNK=1: A rows map into x[B,SEQLEN,D] for chunk `chunk` (row r -> batch r/256, seq chunk*256 + r%256).
template <int TRA, int TRB, int ACHUNK, int EPI>
__global__ __launch_bounds__(256) void gemm64(
    const float* __restrict__ A, const float* __restrict__ B,
    float* __restrict__ C, float* __restrict__ C2,
    const float* __restrict__ aux, float* __restrict__ S,
    const float* __restrict__ sa, const float* __restrict__ sl,
    const float* __restrict__ sd, const int* __restrict__ su,
    int M, int N, int K, int chunk)
{
    constexpr int BM = 64, BN = 64, BK = 16;
    __shared__ float As[BK][BM];
    __shared__ float Bs[BK][BN];

    const int tid = threadIdx.x;
    const int tx = tid & 15;       // 0..15 -> col group
    const int ty = tid >> 4;       // 0..15 -> row group
    const int row0 = blockIdx.y * BM;
    const int col0 = blockIdx.x * BN;

    const float* Abase;
    int lda;
    if (ACHUNK) {
        int b = row0 / CHUNKSZ;
        int s = row0 % CHUNKSZ;
        Abase = A + ((size_t)b * SEQLEN + (size_t)chunk * CHUNKSZ + s) * DD;
        lda = DD;
    } else if (!TRA) {
        Abase = A + (size_t)row0 * K;
        lda = K;
    } else {
        Abase = A + row0;   // element (k, i): Abase[k*M + i]
        lda = M;
    }
    const float* Bbase = (!TRB) ? (B + col0) : (B + (size_t)col0 * K);

    float acc[4][4];
#pragma unroll
    for (int i = 0; i < 4; i++)
#pragma unroll
        for (int j = 0; j < 4; j++) acc[i][j] = 0.0f;

    for (int k0 = 0; k0 < K; k0 += BK) {
        // ---- load A tile into As[kk][i] ----
        if (!TRA || ACHUNK) {
            int idx = tid * 4;           // kk fastest: 4 contiguous k per thread
            int i = idx >> 4;
            int kk = idx & 15;
            float4 av = *(const float4*)(Abase + (size_t)i * lda + k0 + kk);
            As[kk + 0][i] = av.x; As[kk + 1][i] = av.y;
            As[kk + 2][i] = av.z; As[kk + 3][i] = av.w;
        } else {
            int idx = tid * 4;           // i fastest
            int kk = idx >> 6;
            int i = idx & 63;
            float4 av = *(const float4*)(Abase + (size_t)(k0 + kk) * lda + i);
            *(float4*)&As[kk][i] = av;
        }
        // ---- load B tile into Bs[kk][j] ----
        if (!TRB) {
            int idx = tid * 4;           // j fastest
            int kk = idx >> 6;
            int j = idx & 63;
            float4 bv = *(const float4*)(Bbase + (size_t)(k0 + kk) * N + j);
            *(float4*)&Bs[kk][j] = bv;
        } else {
            int idx = tid * 4;           // kk fastest
            int j = idx >> 4;
            int kk = idx & 15;
            float4 bv = *(const float4*)(Bbase + (size_t)j * K + k0 + kk);
            Bs[kk + 0][j] = bv.x; Bs[kk + 1][j] = bv.y;
            Bs[kk + 2][j] = bv.z; Bs[kk + 3][j] = bv.w;
        }
        __syncthreads();

#pragma unroll
        for (int kk = 0; kk < BK; kk++) {
            float4 a = *(const float4*)&As[kk][ty * 4];
            float4 b = *(const float4*)&Bs[kk][tx * 4];
            float ar[4] = {a.x, a.y, a.z, a.w};
            float br[4] = {b.x, b.y, b.z, b.w};
#pragma unroll
            for (int i = 0; i < 4; i++)
#pragma unroll
                for (int j = 0; j < 4; j++)
                    acc[i][j] = fmaf(ar[i], br[j], acc[i][j]);
        }
        __syncthreads();
    }

    // ---- epilogue ----
    float alpha = 0.0f, lr = 0.0f, decay = 0.0f;
    int um = 1;
    if (EPI == EPI_UPDATE) {
        alpha = sigm(sa[0]); lr = sigm(sl[0]); decay = sigm(sd[0]); um = su[0];
    }
#pragma unroll
    for (int i = 0; i < 4; i++) {
        int r = row0 + ty * 4 + i;
#pragma unroll
        for (int j = 0; j < 4; j++) {
            int c = col0 + tx * 4 + j;
            size_t idx = (size_t)r * N + c;
            float v = acc[i][j];
            if (EPI == EPI_NONE) {
                C[idx] = v;
            } else if (EPI == EPI_GELU_BOTH) {
                C[idx] = geluf(v);
                C2[idx] = gelugrad(v);
            } else if (EPI == EPI_GELU) {
                C[idx] = geluf(v);
            } else if (EPI == EPI_DPRED) {
                C[idx] = (v - aux[idx]) * 3.814697265625e-06f;  // 2/(1024*512)
            } else if (EPI == EPI_MULGP) {
                C[idx] = v * aux[idx];
            } else if (EPI == EPI_UPDATE) {
                if (um) {
                    float s = decay * S[idx] - lr * v;
                    S[idx] = s;
                    C[idx] = (1.0f - alpha) * C[idx] + s;
                }
            }
        }
    }
}

__global__ void init_kernel(const float* __restrict__ w1, const float* __restrict__ w2,
                            float* __restrict__ W1, float* __restrict__ W2,
                            float* __restrict__ S1, float* __restrict__ S2)
{
    int i = blockIdx.x * blockDim.x + threadIdx.x;
    if (i < 524288) {
        W1[i] = w1[i]; S1[i] = 0.0f;
        W2[i] = w2[i]; S2[i] = 0.0f;
    }
}

extern "C" void kernel_launch(void* const* d_in, const int* in_sizes, int n_in,
                              void* d_out, int out_size)
{
    const float* x      = (const float*)d_in[0];
    const float* w_q    = (const float*)d_in[1];
    const float* w_k    = (const float*)d_in[2];
    const float* w_v    = (const float*)d_in[3];
    const float* mem_w1 = (const float*)d_in[4];
    const float* mem_w2 = (const float*)d_in[5];
    const float* alpha_t = (const float*)d_in[6];
    const float* lr_t    = (const float*)d_in[7];
    const float* decay_t = (const float*)d_in[8];
    const int*   update_mem = (const int*)d_in[9];
    float* out = (float*)d_out;

    float* scratch = nullptr;
    cudaGetSymbolAddress((void**)&scratch, g_scratch);

    float* W1 = scratch + OFF_W1;
    float* W2 = scratch + OFF_W2;
    float* S1 = scratch + OFF_S1;
    float* S2 = scratch + OFF_S2;
    float* Kb = scratch + OFF_K;
    float* Vb = scratch + OFF_V;
    float* DP = scratch + OFF_DP;
    float* HG = scratch + OFF_HG;
    float* GP = scratch + OFF_GP;
    float* DH = scratch + OFF_DH;
    float* Q  = scratch + OFF_Q;
    float* HQ = scratch + OFF_HQ;

    init_kernel<<<(524288 + 255) / 256, 256>>>(mem_w1, mem_w2, W1, W2, S1, S2);

    const dim3 thr(256);
    for (int c = 0; c < NCHUNK; c++) {
        // k = Xc @ w_k : [1024,512]
        gemm64<0, 0, 1, EPI_NONE><<<dim3(512 / 64, ROWS / 64), thr>>>(
            x, w_k, Kb, nullptr, nullptr, nullptr, nullptr, nullptr, nullptr, nullptr,
            ROWS, 512, 512, c);
        // v = Xc @ w_v : [1024,512]
        gemm64<0, 0, 1, EPI_NONE><<<dim3(512 / 64, ROWS / 64), thr>>>(
            x, w_v, Vb, nullptr, nullptr, nullptr, nullptr, nullptr, nullptr, nullptr,
            ROWS, 512, 512, c);
        // h = k @ W1 : [1024,1024]; HG = gelu(h), GP = gelu'(h)
        gemm64<0, 0, 0, EPI_GELU_BOTH><<<dim3(HID / 64, ROWS / 64), thr>>>(
            Kb, W1, HG, GP, nullptr, nullptr, nullptr, nullptr, nullptr, nullptr,
            ROWS, HID, 512, 0);
        // dpred = (HG @ W2 - v) * 2/N : [1024,512]
        gemm64<0, 0, 0, EPI_DPRED><<<dim3(512 / 64, ROWS / 64), thr>>>(
            HG, W2, DP, nullptr, Vb, nullptr, nullptr, nullptr, nullptr, nullptr,
            ROWS, 512, HID, 0);
        // dh = (dpred @ W2^T) * GP : [1024,1024]   (uses OLD W2)
        gemm64<0, 1, 0, EPI_MULGP><<<dim3(HID / 64, ROWS / 64), thr>>>(
            DP, W2, DH, nullptr, GP, nullptr, nullptr, nullptr, nullptr, nullptr,
            ROWS, HID, 512, 0);
        // g2 = HG^T @ dpred : [1024,512]; then S2 = decay*S2 - lr*g2; W2 = (1-a)*W2 + S2
        gemm64<1, 0, 0, EPI_UPDATE><<<dim3(512 / 64, HID / 64), thr>>>(
            HG, DP, W2, nullptr, nullptr, S2, alpha_t, lr_t, decay_t, update_mem,
            HID, 512, ROWS, 0);
        // g1 = k^T @ dh : [512,1024]; then S1/W1 update
        gemm64<1, 0, 0, EPI_UPDATE><<<dim3(HID / 64, 512 / 64), thr>>>(
            Kb, DH, W1, nullptr, nullptr, S1, alpha_t, lr_t, decay_t, update_mem,
            512, HID, ROWS, 0);
    }

    const int MQ = BATCH * SEQLEN;  // 16384
    // q = x @ w_q : [16384,512]
    gemm64<0, 0, 0, EPI_NONE><<<dim3(512 / 64, MQ / 64), thr>>>(
        x, w_q, Q, nullptr, nullptr, nullptr, nullptr, nullptr, nullptr, nullptr,
        MQ, 512, 512, 0);
    // hq = gelu(q @ W1) : [16384,1024]
    gemm64<0, 0, 0, EPI_GELU><<<dim3(HID / 64, MQ / 64), thr>>>(
        Q, W1, HQ, nullptr, nullptr, nullptr, nullptr, nullptr, nullptr, nullptr,
        MQ, HID, 512, 0);
    // out = hq @ W2 : [16384,512]
    gemm64<0, 0, 0, EPI_NONE><<<dim3(512 / 64, MQ / 64), thr>>>(
        HQ, W2, out, nullptr, nullptr, nullptr, nullptr, nullptr, nullptr, nullptr,
        MQ, 512, HID, 0);
}